// round 16
// baseline (speedup 1.0000x reference)
#include <cuda_runtime.h>
#include <math.h>

#define DD      1024
#define KK      8       // elements per thread per row
#define RR      2       // rows per unit (pair batching, float2-interleaved)
#define UNITS   2       // stack-units per block
#define UT      128     // threads per unit (4 warps)
#define THREADS (UNITS * UT)
#define STACK   4
#define SH2     1088    // float2 slots per unit: max slot(1023)=1086

// In-register FWHT over the 3 bits of k (8 values).
__device__ __forceinline__ void fwht_reg8(float v[KK]) {
#pragma unroll
    for (int b = 1; b < KK; b <<= 1) {
#pragma unroll
        for (int k = 0; k < KK; k++) {
            if ((k & b) == 0) {
                float a0 = v[k], a1 = v[k | b];
                v[k]     = a0 + a1;
                v[k | b] = a0 - a1;
            }
        }
    }
}

// Cross-lane butterfly: element bit (3+log2 m) == lane bit log2 m in B layout.
__device__ __forceinline__ void fwht_shfl(float v[KK], int lane, int m) {
#pragma unroll
    for (int k = 0; k < KK; k++) {
        float w = __shfl_xor_sync(0xffffffffu, v[k], m);
        v[k] = (lane & m) ? (w - v[k]) : (v[k] + w);
    }
}

// Padded float2 addressing: slot(e) = e + (e>>4)
//  B sweep e = 8t+k (k<8): slot = 8t + (t>>1) + k
//      16-lane phase: (8t+(t>>1)) mod 16 = {u, u+8} over t=2u/2u+1 -> distinct, CF
//  A sweep e = 128k+t:     slot = 136k + t + (t>>4)   (lane-consecutive, CF)
//  gather  e = p:          slot = p + (p>>4)          (random, ~2x replay)

__global__ __launch_bounds__(THREADS, 4)   // <=64 regs; v[2][8] resident
void FastFoodLayerDense_kernel(const float* __restrict__ x,
                               const float* __restrict__ Bm,
                               const float* __restrict__ G,
                               const float* __restrict__ S,
                               const float* __restrict__ bias,
                               const int*   __restrict__ P,
                               float*       __restrict__ out,
                               int nrows)
{
    __shared__ float2 sh[UNITS][SH2];   // 17.4 KB

    const int tid  = threadIdx.x;
    const int u    = tid >> 7;                       // unit within block
    const int t    = tid & 127;                      // thread within unit
    const int lane = tid & 31;
    const int s    = ((blockIdx.x & 1) << 1) | u;    // stack index
    const int r0   = (blockIdx.x >> 1) * RR;         // first row of pair

    const int bBase = 8 * t + (t >> 1);    // B-sweep float2 base slot
    const int aOff  = t + (t >> 4);        // A-sweep float2 offset

    float2* shu = sh[u];

    int rows[RR];
    bool wr[RR];
#pragma unroll
    for (int r = 0; r < RR; r++) {
        int rr = r0 + r;
        wr[r]   = rr < nrows;
        rows[r] = wr[r] ? rr : (nrows - 1);   // clamp loads, guard stores
    }

    float v[RR][KK];

    // ===== load x*B (B layout e = 8t+k, vectorized; B loaded once per pair) =====
    const float4* Bv = (const float4*)(Bm + s * DD);
#pragma unroll
    for (int j = 0; j < 2; j++) {
        float4 bv = Bv[t * 2 + j];
#pragma unroll
        for (int r = 0; r < RR; r++) {
            const float4* xv = (const float4*)(x + (size_t)rows[r] * DD);
            float4 a = xv[t * 2 + j];
            v[r][4*j+0] = a.x * bv.x;  v[r][4*j+1] = a.y * bv.y;
            v[r][4*j+2] = a.z * bv.z;  v[r][4*j+3] = a.w * bv.w;
        }
    }

    // ===== WHT #1 low: bits 0-2 (reg) + 3-6 (shfl) =====
#pragma unroll
    for (int r = 0; r < RR; r++) {
        fwht_reg8(v[r]);
        fwht_shfl(v[r], lane, 1);
        fwht_shfl(v[r], lane, 2);
        fwht_shfl(v[r], lane, 4);
        fwht_shfl(v[r], lane, 8);
    }

    // ===== RT1: B -> A (row-interleaved STS.64/LDS.64) =====
#pragma unroll
    for (int k = 0; k < KK; k++)
        shu[bBase + k] = make_float2(v[0][k], v[1][k]);
    __syncthreads();
#pragma unroll
    for (int k = 0; k < KK; k++) {
        float2 a = shu[136 * k + aOff];
        v[0][k] = a.x;  v[1][k] = a.y;
    }

    // ===== WHT #1 high: bits 7-9 (A layout, regs) =====
#pragma unroll
    for (int r = 0; r < RR; r++) fwht_reg8(v[r]);

    // ===== RT2: stage element-ordered (A layout), then permute-gather * G =====
    __syncthreads();                       // WAR on buffer
#pragma unroll
    for (int k = 0; k < KK; k++)
        shu[136 * k + aOff] = make_float2(v[0][k], v[1][k]);
    __syncthreads();

    const int*   Ps = P + s * DD;
    const float* Gs = G + s * DD;
#pragma unroll
    for (int k = 0; k < KK; k++) {
        int e = k * 128 + t;
        int p = Ps[e] - s * DD;            // segment s maps within stack s
        float2 a = shu[p + (p >> 4)];      // one LDS.64 serves both rows
        float g  = Gs[e];
        v[0][k] = a.x * g;  v[1][k] = a.y * g;
    }

    // ===== WHT #2 high: bits 7-9 (A layout) =====
#pragma unroll
    for (int r = 0; r < RR; r++) fwht_reg8(v[r]);

    // ===== RT3: A -> B =====
    __syncthreads();                       // WAR on buffer
#pragma unroll
    for (int k = 0; k < KK; k++)
        shu[136 * k + aOff] = make_float2(v[0][k], v[1][k]);
    __syncthreads();
#pragma unroll
    for (int k = 0; k < KK; k++) {
        float2 a = shu[bBase + k];
        v[0][k] = a.x;  v[1][k] = a.y;
    }

    // ===== WHT #2 low: bits 0-2 (reg) + 3-6 (shfl) =====
#pragma unroll
    for (int r = 0; r < RR; r++) {
        fwht_reg8(v[r]);
        fwht_shfl(v[r], lane, 1);
        fwht_shfl(v[r], lane, 2);
        fwht_shfl(v[r], lane, 4);
        fwht_shfl(v[r], lane, 8);
    }

    // ===== scale, cos/sin, vectorized stores (S/bias loaded once per pair) =====
    const float4* S4  = (const float4*)(S + s * DD);
    const float4* bc4 = (const float4*)(bias + s * DD);
    const float4* bs4 = (const float4*)(bias + STACK * DD + s * DD);
    const float scale = 0.03125f;   // 1/(sigma*sqrt(D))
    const float amp   = 0.03125f;   // sqrt(1/D)
#pragma unroll
    for (int j = 0; j < 2; j++) {
        float4 sv = S4[t * 2 + j];
        float4 bc = bc4[t * 2 + j];
        float4 bs = bs4[t * 2 + j];
#pragma unroll
        for (int r = 0; r < RR; r++) {
            if (!wr[r]) continue;
            float sn, cs;
            float4 co, si;
            __sincosf(v[r][4*j+0] * (scale * sv.x), &sn, &cs);
            co.x = fmaf(amp, cs, bc.x);  si.x = fmaf(amp, sn, bs.x);
            __sincosf(v[r][4*j+1] * (scale * sv.y), &sn, &cs);
            co.y = fmaf(amp, cs, bc.y);  si.y = fmaf(amp, sn, bs.y);
            __sincosf(v[r][4*j+2] * (scale * sv.z), &sn, &cs);
            co.z = fmaf(amp, cs, bc.z);  si.z = fmaf(amp, sn, bs.z);
            __sincosf(v[r][4*j+3] * (scale * sv.w), &sn, &cs);
            co.w = fmaf(amp, cs, bc.w);  si.w = fmaf(amp, sn, bs.w);
            float* orow = out + (size_t)rows[r] * (2 * STACK * DD);
            ((float4*)(orow + s * DD))[t * 2 + j]              = co;
            ((float4*)(orow + STACK * DD + s * DD))[t * 2 + j] = si;
        }
    }
}

extern "C" void kernel_launch(void* const* d_in, const int* in_sizes, int n_in,
                              void* d_out, int out_size)
{
    // metadata order: x, B, G, S, bias, H (unused), P
    const float* x    = (const float*)d_in[0];
    const float* Bm   = (const float*)d_in[1];
    const float* G    = (const float*)d_in[2];
    const float* S    = (const float*)d_in[3];
    const float* bias = (const float*)d_in[4];
    const int*   P    = (const int*)  d_in[6];

    int nrows  = in_sizes[0] / DD;                 // 8192
    int pairs  = (nrows + RR - 1) / RR;            // 4096
    int blocks = pairs * (STACK / UNITS);          // 8192 (2 stack-units/block)

    FastFoodLayerDense_kernel<<<blocks, THREADS>>>(
        x, Bm, G, S, bias, P, (float*)d_out, nrows);
}